// round 11
// baseline (speedup 1.0000x reference)
#include <cuda_runtime.h>
#include <cuda_fp16.h>
#include <cstdint>

#define NB 8
#define NN 2048
#define NF 128

// ---- scratch (device globals; no runtime allocation allowed) ----
__device__ float  g_d[NB * NN];                 // d^-1/2 per (b,n)
__device__ __half g_yt[(size_t)NB * NF * NN];   // fp16 z[b][f][m] = (x W^T), unscaled

// ----------------------------------------------------------------
__device__ __forceinline__ uint32_t smem_u32(const void* p) {
    uint32_t a;
    asm("{ .reg .u64 t; cvta.to.shared.u64 t, %1; cvt.u32.u64 %0, t; }"
        : "=r"(a) : "l"(p));
    return a;
}

__device__ __forceinline__ void mma_f16(float* c, const uint32_t* a, const uint32_t* b) {
    asm volatile(
        "mma.sync.aligned.m16n8k16.row.col.f32.f16.f16.f32 "
        "{%0,%1,%2,%3},{%4,%5,%6,%7},{%8,%9},{%0,%1,%2,%3};"
        : "+f"(c[0]), "+f"(c[1]), "+f"(c[2]), "+f"(c[3])
        : "r"(a[0]), "r"(a[1]), "r"(a[2]), "r"(a[3]), "r"(b[0]), "r"(b[1]));
}

__device__ __forceinline__ void ldsm_x4(uint32_t* r, uint32_t addr) {
    asm volatile("ldmatrix.sync.aligned.m8n8.x4.shared.b16 {%0,%1,%2,%3}, [%4];"
                 : "=r"(r[0]), "=r"(r[1]), "=r"(r[2]), "=r"(r[3]) : "r"(addr));
}

__device__ __forceinline__ void cp16(uint32_t dst, const void* src) {
    asm volatile("cp.async.cg.shared.global [%0], [%1], 16;"
                 :: "r"(dst), "l"(src) : "memory");
}

// ----------------------------------------------------------------
// Kernel 1: degree -> d^-1/2.  Pure read pass, one warp per row.
// ----------------------------------------------------------------
__global__ __launch_bounds__(256)
void degree_kernel(const float* __restrict__ adj) {
    int row  = blockIdx.x * 8 + (threadIdx.x >> 5);
    int lane = threadIdx.x & 31;
    const float4* p = (const float4*)(adj + (size_t)row * NN);
    float s = 0.f;
    #pragma unroll
    for (int i = lane; i < NN / 8; i += 32) {   // 8 iterations, 2x LDG.128 each
        float4 v0 = __ldcs(p + 2 * i);
        float4 v1 = __ldcs(p + 2 * i + 1);
        s += ((v0.x + v0.y) + (v0.z + v0.w)) + ((v1.x + v1.y) + (v1.z + v1.w));
    }
    #pragma unroll
    for (int o = 16; o; o >>= 1) s += __shfl_xor_sync(0xFFFFFFFFu, s, o);
    if (lane == 0) g_d[row] = rsqrtf(s + 1.0f);
}

// ----------------------------------------------------------------
// Kernel 2 (fp16): g_yt[b][f][m] = fp16( sum_k x[m,k] * W[f,k] )   (UNSCALED)
// CTA tile 64(m) x 128(f), K=128 in 4 chunks of 32, m16n8k16.
// ----------------------------------------------------------------
__global__ __launch_bounds__(256)
void xw_kernel(const float* __restrict__ x, const float* __restrict__ W) {
    __shared__ __half As[64][40];
    __shared__ __half Ws[128][40];

    const int tid  = threadIdx.x;
    const int lane = tid & 31;
    const int wid  = tid >> 5;
    const int wm   = wid >> 2;
    const int wn   = wid & 3;
    const int lr   = lane >> 2;
    const int lc   = lane & 3;
    const int m0   = blockIdx.x * 64;

    float cacc[2][4][4];
    #pragma unroll
    for (int mi = 0; mi < 2; mi++)
        #pragma unroll
        for (int ni = 0; ni < 4; ni++)
            #pragma unroll
            for (int j = 0; j < 4; j++) cacc[mi][ni][j] = 0.f;

    for (int kt = 0; kt < 4; ++kt) {
        const int k0 = kt * 32;
        #pragma unroll
        for (int i = 0; i < 2; i++) {
            int q = tid + i * 256;
            int r = q >> 3;
            int c4 = (q & 7) * 4;
            float4 v = *(const float4*)(x + (size_t)(m0 + r) * NF + k0 + c4);
            *(__half2*)&As[r][c4]     = __floats2half2_rn(v.x, v.y);
            *(__half2*)&As[r][c4 + 2] = __floats2half2_rn(v.z, v.w);
        }
        #pragma unroll
        for (int i = 0; i < 4; i++) {
            int q = tid + i * 256;
            int r = q >> 3;
            int c4 = (q & 7) * 4;
            float4 v = *(const float4*)(W + (size_t)r * NF + k0 + c4);
            *(__half2*)&Ws[r][c4]     = __floats2half2_rn(v.x, v.y);
            *(__half2*)&Ws[r][c4 + 2] = __floats2half2_rn(v.z, v.w);
        }
        __syncthreads();

        #pragma unroll
        for (int ks = 0; ks < 2; ks++) {
            const int kk = ks * 16;
            uint32_t a[2][4], bq[4][2];
            #pragma unroll
            for (int mi = 0; mi < 2; mi++) {
                int ar = wm * 32 + mi * 16 + lr;
                a[mi][0] = *(const uint32_t*)(&As[ar][kk + 2 * lc]);
                a[mi][1] = *(const uint32_t*)(&As[ar + 8][kk + 2 * lc]);
                a[mi][2] = *(const uint32_t*)(&As[ar][kk + 2 * lc + 8]);
                a[mi][3] = *(const uint32_t*)(&As[ar + 8][kk + 2 * lc + 8]);
            }
            #pragma unroll
            for (int ni = 0; ni < 4; ni++) {
                int bc = wn * 32 + ni * 8 + lr;
                bq[ni][0] = *(const uint32_t*)(&Ws[bc][kk + 2 * lc]);
                bq[ni][1] = *(const uint32_t*)(&Ws[bc][kk + 2 * lc + 8]);
            }
            #pragma unroll
            for (int mi = 0; mi < 2; mi++)
                #pragma unroll
                for (int ni = 0; ni < 4; ni++)
                    mma_f16(cacc[mi][ni], a[mi], bq[ni]);
        }
        __syncthreads();
    }

    #pragma unroll
    for (int mi = 0; mi < 2; mi++) {
        #pragma unroll
        for (int ri = 0; ri < 2; ri++) {
            const int gm   = m0 + wm * 32 + mi * 16 + lr + ri * 8;
            const int b    = gm >> 11;
            const int mloc = gm & (NN - 1);
            #pragma unroll
            for (int ni = 0; ni < 4; ni++) {
                int f = wn * 32 + ni * 8 + 2 * lc;
                g_yt[(size_t)(b * NF + f)     * NN + mloc] =
                    __float2half_rn(cacc[mi][ni][ri * 2 + 0]);
                g_yt[(size_t)(b * NF + f + 1) * NN + mloc] =
                    __float2half_rn(cacc[mi][ni][ri * 2 + 1]);
            }
        }
    }
}

// ----------------------------------------------------------------
// Kernel 3: out[b,n,f] = d[n] * sum_m ((adj+I)[n,m]*d[m]) * z[m,f] + bias[f]
// CTA 64(n) x 128(f), K=2048 in 32 chunks of 64.
// 256 threads, 8 warps (2x4), warp tile 32x32, 2 CTAs/SM.
//   A: fp32 adj LDG -> regs (1 chunk ahead) -> +I, x d[m], fp16 cvt -> STS
//      double-buffered smem, ONE sync per chunk.
//   B: g_yt fp16 via 3-stage cp.async (early issue).
// ----------------------------------------------------------------
#define KCH2 64
#define NCH2 (NN / KCH2)       // 32
#define ASTR 72                // halfs per row (144B; conflict-free for LDSM/STS)
#define A_HALFS (64 * ASTR)    // one A buffer
#define B_HALFS (128 * ASTR)   // one B stage
#define A_BYTES (A_HALFS * 2)
#define B_BYTES (B_HALFS * 2)
#define SMEM_BYTES (2 * A_BYTES + 3 * B_BYTES)   // 18432 + 55296 = 73728

__global__ __launch_bounds__(256, 2)
void adj_mma_kernel(const float* __restrict__ adj,
                    const float* __restrict__ bias,
                    float* __restrict__ out) {
    extern __shared__ __half hsm[];
    const uint32_t hbase = smem_u32(hsm);
    __half* bbase_sm = hsm + 2 * A_HALFS;

    const int tid  = threadIdx.x;
    const int lane = tid & 31;
    const int wid  = tid >> 5;
    const int wm   = wid >> 2;        // 0..1 over n (32 rows each)
    const int wn   = wid & 3;         // 0..3 over f (32 cols each)
    const int lr   = lane >> 2;
    const int lc   = lane & 3;
    const int row0  = blockIdx.x * 64;
    const int batch = blockIdx.y;

    const float*  Ag = adj + ((size_t)batch * NN + row0) * NN;
    const __half* Bg = g_yt + (size_t)batch * NF * NN;
    const float*  dg = g_d + batch * NN;

    // A per-thread map: row ar (0..63), 16 consecutive cols at acb
    const int ar  = tid >> 2;
    const int acb = (tid & 3) * 16;

    const uint32_t aoff =
        (uint32_t)((wm * 32 + (lane & 7) + ((lane >> 3) & 1) * 8) * ASTR * 2
                   + ((lane >> 4) & 1) * 16);
    const uint32_t boff =
        (uint32_t)((wn * 32 + (lane & 7) + ((lane >> 4) & 1) * 8) * ASTR * 2
                   + ((lane >> 3) & 1) * 16);

    float4 pa[4];
    auto ldgA = [&](int c) {
        const float* src = Ag + (size_t)ar * NN + c * KCH2 + acb;
        #pragma unroll
        for (int i = 0; i < 4; i++) pa[i] = __ldcs((const float4*)src + i);
    };
    auto stsA = [&](int c, int s) {
        const int k0 = c * KCH2;
        const float4* dp = (const float4*)(dg + k0 + acb);
        int diag = (row0 + ar) - (k0 + acb);       // j in [0,16) if on diagonal
        __half* dst = hsm + s * A_HALFS + ar * ASTR + acb;
        uint32_t hh[8];
        #pragma unroll
        for (int i = 0; i < 4; i++) {
            float4 v = pa[i];
            float4 dv = dp[i];
            int dl = diag - 4 * i;
            if (dl >= 0 && dl < 4) ((float*)&v)[dl] += 1.0f;
            __half2 h0 = __floats2half2_rn(v.x * dv.x, v.y * dv.y);
            __half2 h1 = __floats2half2_rn(v.z * dv.z, v.w * dv.w);
            hh[2 * i]     = *(const uint32_t*)&h0;
            hh[2 * i + 1] = *(const uint32_t*)&h1;
        }
        *(uint4*)dst       = make_uint4(hh[0], hh[1], hh[2], hh[3]);
        *(uint4*)(dst + 8) = make_uint4(hh[4], hh[5], hh[6], hh[7]);
    };
    auto cpB = [&](int c, int s) {
        __half* Bs = bbase_sm + s * B_HALFS;
        const int k0 = c * KCH2;
        #pragma unroll
        for (int i = 0; i < 4; i++) {           // B: 128 rows x 64 halfs
            int q = tid + i * 256;
            int r = q >> 3;
            int o = (q & 7) * 8;
            cp16(smem_u32(Bs + r * ASTR + o), Bg + (size_t)r * NN + k0 + o);
        }
        asm volatile("cp.async.commit_group;" ::: "memory");
    };

    float cacc[2][4][4];
    #pragma unroll
    for (int mi = 0; mi < 2; mi++)
        #pragma unroll
        for (int ni = 0; ni < 4; ni++)
            #pragma unroll
            for (int j = 0; j < 4; j++) cacc[mi][ni][j] = 0.f;

    // ---- prologue ----
    cpB(0, 0);
    cpB(1, 1);
    ldgA(0);
    stsA(0, 0);
    ldgA(1);

    for (int c = 0; c < NCH2; c++) {
        const int s = c % 3;
        if (c < NCH2 - 1)
            asm volatile("cp.async.wait_group 1;" ::: "memory");
        else
            asm volatile("cp.async.wait_group 0;" ::: "memory");
        __syncthreads();   // B(c) landed; abuf[(c+1)&1] free (compute(c-1) done)

        if (c + 2 < NCH2) cpB(c + 2, (c + 2) % 3);
        if (c + 1 < NCH2) {
            stsA(c + 1, (c + 1) & 1);            // regs hold A(c+1)
            if (c + 2 < NCH2) ldgA(c + 2);
        }

        const uint32_t As_u = hbase + (c & 1) * A_BYTES;
        const uint32_t Bs_u = hbase + 2 * A_BYTES + s * B_BYTES;

        #pragma unroll
        for (int ks = 0; ks < 4; ks++) {
            const uint32_t kb = ks * 32;          // bytes (16 halfs)
            uint32_t a[2][4], bt[2][4];
            ldsm_x4(a[0], As_u + aoff + kb);
            ldsm_x4(a[1], As_u + aoff + 16 * ASTR * 2 + kb);
            ldsm_x4(bt[0], Bs_u + boff + kb);
            ldsm_x4(bt[1], Bs_u + boff + 16 * ASTR * 2 + kb);
            #pragma unroll
            for (int mi = 0; mi < 2; mi++)
                #pragma unroll
                for (int ni = 0; ni < 4; ni++)
                    mma_f16(cacc[mi][ni], a[mi], &bt[ni >> 1][(ni & 1) * 2]);
        }
    }

    // ---- epilogue: out = d[n]*acc + bias ----
    #pragma unroll
    for (int mi = 0; mi < 2; mi++) {
        #pragma unroll
        for (int ri = 0; ri < 2; ri++) {
            const int grow = row0 + wm * 32 + mi * 16 + lr + ri * 8;
            const float dn = dg[grow];
            float* po = out + ((size_t)(batch * NN + grow)) * NF;
            #pragma unroll
            for (int ni = 0; ni < 4; ni++) {
                int f = wn * 32 + ni * 8 + 2 * lc;
                float2 bv = *(const float2*)(bias + f);
                float2 v;
                v.x = dn * cacc[mi][ni][ri * 2 + 0] + bv.x;
                v.y = dn * cacc[mi][ni][ri * 2 + 1] + bv.y;
                *(float2*)(po + f) = v;
            }
        }
    }
}

// ----------------------------------------------------------------
extern "C" void kernel_launch(void* const* d_in, const int* in_sizes, int n_in,
                              void* d_out, int out_size) {
    const float *x = nullptr, *adj = nullptr, *W = nullptr, *bias = nullptr;
    for (int i = 0; i < n_in; i++) {
        int s = in_sizes[i];
        if (s == NB * NN * NN)      adj  = (const float*)d_in[i];
        else if (s == NB * NN * NF) x    = (const float*)d_in[i];
        else if (s == NF * NF)      W    = (const float*)d_in[i];
        else if (s == NF)           bias = (const float*)d_in[i];
    }
    float* out = (float*)d_out;

    cudaFuncSetAttribute(adj_mma_kernel,
                         cudaFuncAttributeMaxDynamicSharedMemorySize, SMEM_BYTES);

    degree_kernel<<<NB * NN / 8, 256>>>(adj);
    xw_kernel<<<NB * NN / 64, 256>>>(x, W);
    adj_mma_kernel<<<dim3(NN / 64, NB), 256, SMEM_BYTES>>>(adj, bias, out);
}

// round 12
// speedup vs baseline: 1.3071x; 1.3071x over previous
#include <cuda_runtime.h>
#include <cuda_fp16.h>
#include <cstdint>

#define NB 8
#define NN 2048
#define NF 128

// ---- scratch (device globals; no runtime allocation allowed) ----
__device__ float  g_d[NB * NN];                     // d^-1/2 per (b,n)
__device__ __half g_yt[(size_t)NB * NF * NN];       // fp16 z[b][f][m]; scaled in-place by d[m]
__device__ __half g_adj16[(size_t)NB * NN * NN];    // fp16( adj + I ), 67 MB

// ----------------------------------------------------------------
__device__ __forceinline__ uint32_t smem_u32(const void* p) {
    uint32_t a;
    asm("{ .reg .u64 t; cvta.to.shared.u64 t, %1; cvt.u32.u64 %0, t; }"
        : "=r"(a) : "l"(p));
    return a;
}

__device__ __forceinline__ void mma_f16(float* c, const uint32_t* a, const uint32_t* b) {
    asm volatile(
        "mma.sync.aligned.m16n8k16.row.col.f32.f16.f16.f32 "
        "{%0,%1,%2,%3},{%4,%5,%6,%7},{%8,%9},{%0,%1,%2,%3};"
        : "+f"(c[0]), "+f"(c[1]), "+f"(c[2]), "+f"(c[3])
        : "r"(a[0]), "r"(a[1]), "r"(a[2]), "r"(a[3]), "r"(b[0]), "r"(b[1]));
}

__device__ __forceinline__ void ldsm_x4(uint32_t* r, uint32_t addr) {
    asm volatile("ldmatrix.sync.aligned.m8n8.x4.shared.b16 {%0,%1,%2,%3}, [%4];"
                 : "=r"(r[0]), "=r"(r[1]), "=r"(r[2]), "=r"(r[3]) : "r"(addr));
}

__device__ __forceinline__ void cp16(uint32_t dst, const void* src) {
    asm volatile("cp.async.cg.shared.global [%0], [%1], 16;"
                 :: "r"(dst), "l"(src) : "memory");
}

// ----------------------------------------------------------------
// Kernel 1: degree -> d^-1/2 AND fp16(adj + I) -> g_adj16.
// One warp per row; 32B in / 16B out per lane-iteration (STG.128).
// ----------------------------------------------------------------
__global__ __launch_bounds__(256)
void degree_kernel(const float* __restrict__ adj) {
    int row  = blockIdx.x * 8 + (threadIdx.x >> 5);   // 0 .. NB*NN-1
    int lane = threadIdx.x & 31;
    int n    = row & (NN - 1);                 // diag index within batch
    const float4* p = (const float4*)(adj + (size_t)row * NN);
    __half* q = g_adj16 + (size_t)row * NN;
    float s = 0.f;
    #pragma unroll
    for (int i = lane; i < NN / 8; i += 32) {  // 8 iterations
        float4 v0 = __ldcs(p + 2 * i);
        float4 v1 = __ldcs(p + 2 * i + 1);
        s += ((v0.x + v0.y) + (v0.z + v0.w)) + ((v1.x + v1.y) + (v1.z + v1.w));
        int col = i * 8;
        int d = n - col;
        if (d >= 0 && d < 8) {                 // fold self-loop
            if (d < 4) ((float*)&v0)[d] += 1.0f;
            else       ((float*)&v1)[d - 4] += 1.0f;
        }
        __half2 h0 = __floats2half2_rn(v0.x, v0.y);
        __half2 h1 = __floats2half2_rn(v0.z, v0.w);
        __half2 h2 = __floats2half2_rn(v1.x, v1.y);
        __half2 h3 = __floats2half2_rn(v1.z, v1.w);
        float4 pk;
        pk.x = __uint_as_float(*(const uint32_t*)&h0);
        pk.y = __uint_as_float(*(const uint32_t*)&h1);
        pk.z = __uint_as_float(*(const uint32_t*)&h2);
        pk.w = __uint_as_float(*(const uint32_t*)&h3);
        __stcs((float4*)(q + col), pk);
    }
    #pragma unroll
    for (int o = 16; o; o >>= 1) s += __shfl_xor_sync(0xFFFFFFFFu, s, o);
    if (lane == 0) g_d[row] = rsqrtf(s + 1.0f);
}

// ----------------------------------------------------------------
// Kernel 2 (fp16): g_yt[b][f][m] = fp16( sum_k x[m,k] * W[f,k] )  (UNSCALED)
// CTA tile 64(m) x 128(f), K=128 in 4 chunks of 32, m16n8k16.
// Independent of degree -> runs concurrently on a forked stream.
// ----------------------------------------------------------------
__global__ __launch_bounds__(256)
void xw_kernel(const float* __restrict__ x, const float* __restrict__ W) {
    __shared__ __half As[64][40];
    __shared__ __half Ws[128][40];

    const int tid  = threadIdx.x;
    const int lane = tid & 31;
    const int wid  = tid >> 5;
    const int wm   = wid >> 2;
    const int wn   = wid & 3;
    const int lr   = lane >> 2;
    const int lc   = lane & 3;
    const int m0   = blockIdx.x * 64;

    float cacc[2][4][4];
    #pragma unroll
    for (int mi = 0; mi < 2; mi++)
        #pragma unroll
        for (int ni = 0; ni < 4; ni++)
            #pragma unroll
            for (int j = 0; j < 4; j++) cacc[mi][ni][j] = 0.f;

    for (int kt = 0; kt < 4; ++kt) {
        const int k0 = kt * 32;
        #pragma unroll
        for (int i = 0; i < 2; i++) {
            int q = tid + i * 256;
            int r = q >> 3;
            int c4 = (q & 7) * 4;
            float4 v = *(const float4*)(x + (size_t)(m0 + r) * NF + k0 + c4);
            *(__half2*)&As[r][c4]     = __floats2half2_rn(v.x, v.y);
            *(__half2*)&As[r][c4 + 2] = __floats2half2_rn(v.z, v.w);
        }
        #pragma unroll
        for (int i = 0; i < 4; i++) {
            int q = tid + i * 256;
            int r = q >> 3;
            int c4 = (q & 7) * 4;
            float4 v = *(const float4*)(W + (size_t)r * NF + k0 + c4);
            *(__half2*)&Ws[r][c4]     = __floats2half2_rn(v.x, v.y);
            *(__half2*)&Ws[r][c4 + 2] = __floats2half2_rn(v.z, v.w);
        }
        __syncthreads();

        #pragma unroll
        for (int ks = 0; ks < 2; ks++) {
            const int kk = ks * 16;
            uint32_t a[2][4], bq[4][2];
            #pragma unroll
            for (int mi = 0; mi < 2; mi++) {
                int ar = wm * 32 + mi * 16 + lr;
                a[mi][0] = *(const uint32_t*)(&As[ar][kk + 2 * lc]);
                a[mi][1] = *(const uint32_t*)(&As[ar + 8][kk + 2 * lc]);
                a[mi][2] = *(const uint32_t*)(&As[ar][kk + 2 * lc + 8]);
                a[mi][3] = *(const uint32_t*)(&As[ar + 8][kk + 2 * lc + 8]);
            }
            #pragma unroll
            for (int ni = 0; ni < 4; ni++) {
                int bc = wn * 32 + ni * 8 + lr;
                bq[ni][0] = *(const uint32_t*)(&Ws[bc][kk + 2 * lc]);
                bq[ni][1] = *(const uint32_t*)(&Ws[bc][kk + 2 * lc + 8]);
            }
            #pragma unroll
            for (int mi = 0; mi < 2; mi++)
                #pragma unroll
                for (int ni = 0; ni < 4; ni++)
                    mma_f16(cacc[mi][ni], a[mi], bq[ni]);
        }
        __syncthreads();
    }

    #pragma unroll
    for (int mi = 0; mi < 2; mi++) {
        #pragma unroll
        for (int ri = 0; ri < 2; ri++) {
            const int gm   = m0 + wm * 32 + mi * 16 + lr + ri * 8;
            const int b    = gm >> 11;
            const int mloc = gm & (NN - 1);
            #pragma unroll
            for (int ni = 0; ni < 4; ni++) {
                int f = wn * 32 + ni * 8 + 2 * lc;
                g_yt[(size_t)(b * NF + f)     * NN + mloc] =
                    __float2half_rn(cacc[mi][ni][ri * 2 + 0]);
                g_yt[(size_t)(b * NF + f + 1) * NN + mloc] =
                    __float2half_rn(cacc[mi][ni][ri * 2 + 1]);
            }
        }
    }
}

// ----------------------------------------------------------------
// Kernel 3: g_yt[b][f][m] *= d^-1/2[b,m]   (8 MB r/w, ~2 us)
// ----------------------------------------------------------------
__global__ __launch_bounds__(512)
void scale_z_kernel() {
    uint32_t idx = blockIdx.x * 512 + threadIdx.x;   // half2 index
    uint32_t L = idx * 2;                            // half index
    uint32_t m = L & (NN - 1);
    uint32_t b = L >> 18;                            // / (NF*NN)
    __half2 v = ((const __half2*)g_yt)[idx];
    float2 f = __half22float2(v);
    float d0 = g_d[(b << 11) + m];
    float d1 = g_d[(b << 11) + m + 1];
    ((__half2*)g_yt)[idx] = __floats2half2_rn(f.x * d0, f.y * d1);
}

// ----------------------------------------------------------------
// Kernel 4: out[b,n,f] = d[n] * sum_m adj16[b,n,m] * yt[b,f,m] + bias[f]
// CTA 64(n) x 128(f), K=2048 in 32 chunks of 64.
// 256 threads, 8 warps (2x4), warp tile 32x32, 2 CTAs/SM.
// 3-stage cp.async pipeline (A and B), EARLY issue; ldmatrix.x4 fragments.
// ----------------------------------------------------------------
#define KCH2 64
#define NCH2 (NN / KCH2)       // 32
#define ASTR 72                // halfs per row (144B; conflict-free for LDSM)
#define A_HALFS (64 * ASTR)
#define B_HALFS (128 * ASTR)
#define STAGE_HALFS (A_HALFS + B_HALFS)
#define STAGE_BYTES (STAGE_HALFS * 2)      // 27648
#define SMEM_BYTES (3 * STAGE_BYTES)       // 82944

__global__ __launch_bounds__(256, 2)
void adj_mma_kernel(const float* __restrict__ bias,
                    float* __restrict__ out) {
    extern __shared__ __half hsm[];
    const uint32_t hbase = smem_u32(hsm);

    const int tid  = threadIdx.x;
    const int lane = tid & 31;
    const int wid  = tid >> 5;
    const int wm   = wid >> 2;        // 0..1 over n (32 rows each)
    const int wn   = wid & 3;         // 0..3 over f (32 cols each)
    const int lr   = lane >> 2;
    const int lc   = lane & 3;
    const int row0  = blockIdx.x * 64;
    const int batch = blockIdx.y;

    const __half* Ag = g_adj16 + ((size_t)batch * NN + row0) * NN;
    const __half* Bg = g_yt + (size_t)batch * NF * NN;

    const uint32_t aoff =
        (uint32_t)((wm * 32 + (lane & 7) + ((lane >> 3) & 1) * 8) * ASTR * 2
                   + ((lane >> 4) & 1) * 16);
    const uint32_t boff =
        (uint32_t)((wn * 32 + (lane & 7) + ((lane >> 4) & 1) * 8) * ASTR * 2
                   + ((lane >> 3) & 1) * 16);

    auto issue = [&](int c, int s) {
        __half* As = hsm + s * STAGE_HALFS;
        __half* Bs = As + A_HALFS;
        const int k0 = c * KCH2;
        #pragma unroll
        for (int i = 0; i < 2; i++) {           // A: 64 rows x 64 halfs
            int q = tid + i * 256;
            int r = q >> 3;
            int o = (q & 7) * 8;
            cp16(smem_u32(As + r * ASTR + o), Ag + (size_t)r * NN + k0 + o);
        }
        #pragma unroll
        for (int i = 0; i < 4; i++) {           // B: 128 rows x 64 halfs
            int q = tid + i * 256;
            int r = q >> 3;
            int o = (q & 7) * 8;
            cp16(smem_u32(Bs + r * ASTR + o), Bg + (size_t)r * NN + k0 + o);
        }
        asm volatile("cp.async.commit_group;" ::: "memory");
    };

    float cacc[2][4][4];
    #pragma unroll
    for (int mi = 0; mi < 2; mi++)
        #pragma unroll
        for (int ni = 0; ni < 4; ni++)
            #pragma unroll
            for (int j = 0; j < 4; j++) cacc[mi][ni][j] = 0.f;

    issue(0, 0);
    issue(1, 1);

    for (int c = 0; c < NCH2; c++) {
        const int s = c % 3;
        if (c < NCH2 - 1)
            asm volatile("cp.async.wait_group 1;" ::: "memory");
        else
            asm volatile("cp.async.wait_group 0;" ::: "memory");
        __syncthreads();

        // EARLY issue: stage (c+2)%3 == (c-1)%3 was last read in iter c-1.
        if (c + 2 < NCH2) issue(c + 2, (c + 2) % 3);

        const uint32_t As_u = hbase + s * STAGE_BYTES;
        const uint32_t Bs_u = As_u + A_HALFS * 2;

        #pragma unroll
        for (int ks = 0; ks < 4; ks++) {
            const uint32_t kb = ks * 32;          // bytes (16 halfs)
            uint32_t a[2][4], bt[2][4];
            ldsm_x4(a[0], As_u + aoff + kb);
            ldsm_x4(a[1], As_u + aoff + 16 * ASTR * 2 + kb);
            ldsm_x4(bt[0], Bs_u + boff + kb);
            ldsm_x4(bt[1], Bs_u + boff + 16 * ASTR * 2 + kb);
            #pragma unroll
            for (int mi = 0; mi < 2; mi++)
                #pragma unroll
                for (int ni = 0; ni < 4; ni++)
                    mma_f16(cacc[mi][ni], a[mi], &bt[ni >> 1][(ni & 1) * 2]);
        }
    }

    // ---- epilogue: out = d[n]*acc + bias ----
    #pragma unroll
    for (int mi = 0; mi < 2; mi++) {
        #pragma unroll
        for (int ri = 0; ri < 2; ri++) {
            const int grow = row0 + wm * 32 + mi * 16 + lr + ri * 8;
            const float dn = g_d[batch * NN + grow];
            float* po = out + ((size_t)(batch * NN + grow)) * NF;
            #pragma unroll
            for (int ni = 0; ni < 4; ni++) {
                int f = wn * 32 + ni * 8 + 2 * lc;
                float2 bv = *(const float2*)(bias + f);
                float2 v;
                v.x = dn * cacc[mi][ni][ri * 2 + 0] + bv.x;
                v.y = dn * cacc[mi][ni][ri * 2 + 1] + bv.y;
                *(float2*)(po + f) = v;
            }
        }
    }
}

// ----------------------------------------------------------------
extern "C" void kernel_launch(void* const* d_in, const int* in_sizes, int n_in,
                              void* d_out, int out_size) {
    const float *x = nullptr, *adj = nullptr, *W = nullptr, *bias = nullptr;
    for (int i = 0; i < n_in; i++) {
        int s = in_sizes[i];
        if (s == NB * NN * NN)      adj  = (const float*)d_in[i];
        else if (s == NB * NN * NF) x    = (const float*)d_in[i];
        else if (s == NF * NF)      W    = (const float*)d_in[i];
        else if (s == NF)           bias = (const float*)d_in[i];
    }
    float* out = (float*)d_out;

    // One-time host-side setup (no device memory involved).
    static cudaStream_t s_xw = nullptr;
    static cudaEvent_t  ev_fork = nullptr, ev_join = nullptr;
    if (s_xw == nullptr) {
        cudaStreamCreateWithFlags(&s_xw, cudaStreamNonBlocking);
        cudaEventCreateWithFlags(&ev_fork, cudaEventDisableTiming);
        cudaEventCreateWithFlags(&ev_join, cudaEventDisableTiming);
        cudaFuncSetAttribute(adj_mma_kernel,
                             cudaFuncAttributeMaxDynamicSharedMemorySize, SMEM_BYTES);
    }

    // Fork: xw (unscaled z) runs concurrently with degree.
    cudaEventRecord(ev_fork, 0);
    cudaStreamWaitEvent(s_xw, ev_fork, 0);
    xw_kernel<<<NB * NN / 64, 256, 0, s_xw>>>(x, W);
    degree_kernel<<<NB * NN / 8, 256>>>(adj);
    cudaEventRecord(ev_join, s_xw);
    cudaStreamWaitEvent(0, ev_join, 0);

    // Join: z *= d[m], then the big MMA.
    scale_z_kernel<<<(NB * NF * NN / 2) / 512, 512>>>();
    adj_mma_kernel<<<dim3(NN / 64, NB), 256, SMEM_BYTES>>>(bias, out);
}

// round 14
// speedup vs baseline: 1.3615x; 1.0416x over previous
#include <cuda_runtime.h>
#include <cuda_fp16.h>
#include <cstdint>

#define NB 8
#define NN 2048
#define NF 128

// ---- scratch (device globals; no runtime allocation allowed) ----
__device__ float  g_d[NB * NN];                     // d^-1/2 per (b,n)
__device__ __half g_yt[(size_t)NB * NF * NN];       // fp16( d[m]*(xW^T)[m,f] ), [b][f][m]
__device__ __half g_adj16[(size_t)NB * NN * NN];    // fp16( adj + I ), 67 MB

// ----------------------------------------------------------------
__device__ __forceinline__ uint32_t smem_u32(const void* p) {
    uint32_t a;
    asm("{ .reg .u64 t; cvta.to.shared.u64 t, %1; cvt.u32.u64 %0, t; }"
        : "=r"(a) : "l"(p));
    return a;
}

__device__ __forceinline__ void mma_f16(float* c, const uint32_t* a, const uint32_t* b) {
    asm volatile(
        "mma.sync.aligned.m16n8k16.row.col.f32.f16.f16.f32 "
        "{%0,%1,%2,%3},{%4,%5,%6,%7},{%8,%9},{%0,%1,%2,%3};"
        : "+f"(c[0]), "+f"(c[1]), "+f"(c[2]), "+f"(c[3])
        : "r"(a[0]), "r"(a[1]), "r"(a[2]), "r"(a[3]), "r"(b[0]), "r"(b[1]));
}

__device__ __forceinline__ void ldsm_x4(uint32_t* r, uint32_t addr) {
    asm volatile("ldmatrix.sync.aligned.m8n8.x4.shared.b16 {%0,%1,%2,%3}, [%4];"
                 : "=r"(r[0]), "=r"(r[1]), "=r"(r[2]), "=r"(r[3]) : "r"(addr));
}

__device__ __forceinline__ void cp16(uint32_t dst, const void* src) {
    asm volatile("cp.async.cg.shared.global [%0], [%1], 16;"
                 :: "r"(dst), "l"(src) : "memory");
}

// ----------------------------------------------------------------
// Kernel 1: degree -> d^-1/2 AND fp16(adj + I) -> g_adj16.
// One warp per row; 32B in / 16B out per lane-iteration (STG.128).
// ----------------------------------------------------------------
__global__ __launch_bounds__(256)
void degree_kernel(const float* __restrict__ adj) {
    int row  = blockIdx.x * 8 + (threadIdx.x >> 5);   // 0 .. NB*NN-1
    int lane = threadIdx.x & 31;
    int n    = row & (NN - 1);                 // diag index within batch
    const float4* p = (const float4*)(adj + (size_t)row * NN);
    __half* q = g_adj16 + (size_t)row * NN;
    float s = 0.f;
    #pragma unroll
    for (int i = lane; i < NN / 8; i += 32) {  // 8 iterations
        float4 v0 = __ldcs(p + 2 * i);
        float4 v1 = __ldcs(p + 2 * i + 1);
        s += ((v0.x + v0.y) + (v0.z + v0.w)) + ((v1.x + v1.y) + (v1.z + v1.w));
        int col = i * 8;
        int d = n - col;
        if (d >= 0 && d < 8) {                 // fold self-loop
            if (d < 4) ((float*)&v0)[d] += 1.0f;
            else       ((float*)&v1)[d - 4] += 1.0f;
        }
        __half2 h0 = __floats2half2_rn(v0.x, v0.y);
        __half2 h1 = __floats2half2_rn(v0.z, v0.w);
        __half2 h2 = __floats2half2_rn(v1.x, v1.y);
        __half2 h3 = __floats2half2_rn(v1.z, v1.w);
        float4 pk;
        pk.x = __uint_as_float(*(const uint32_t*)&h0);
        pk.y = __uint_as_float(*(const uint32_t*)&h1);
        pk.z = __uint_as_float(*(const uint32_t*)&h2);
        pk.w = __uint_as_float(*(const uint32_t*)&h3);
        __stcs((float4*)(q + col), pk);
    }
    #pragma unroll
    for (int o = 16; o; o >>= 1) s += __shfl_xor_sync(0xFFFFFFFFu, s, o);
    if (lane == 0) g_d[row] = rsqrtf(s + 1.0f);
}

// ----------------------------------------------------------------
// Kernel 2 (fp16): g_yt[b][f][m] = fp16( d[m] * sum_k x[m,k] * W[f,k] )
// CTA tile 64(m) x 128(f), K=128 in 4 chunks of 32, m16n8k16.
// ----------------------------------------------------------------
__global__ __launch_bounds__(256)
void xw_kernel(const float* __restrict__ x, const float* __restrict__ W) {
    __shared__ __half As[64][40];
    __shared__ __half Ws[128][40];

    const int tid  = threadIdx.x;
    const int lane = tid & 31;
    const int wid  = tid >> 5;
    const int wm   = wid >> 2;        // 0..1 over m
    const int wn   = wid & 3;         // 0..3 over f
    const int lr   = lane >> 2;
    const int lc   = lane & 3;
    const int m0   = blockIdx.x * 64;

    float cacc[2][4][4];
    #pragma unroll
    for (int mi = 0; mi < 2; mi++)
        #pragma unroll
        for (int ni = 0; ni < 4; ni++)
            #pragma unroll
            for (int j = 0; j < 4; j++) cacc[mi][ni][j] = 0.f;

    for (int kt = 0; kt < 4; ++kt) {
        const int k0 = kt * 32;
        #pragma unroll
        for (int i = 0; i < 2; i++) {
            int q = tid + i * 256;
            int r = q >> 3;
            int c4 = (q & 7) * 4;
            float4 v = *(const float4*)(x + (size_t)(m0 + r) * NF + k0 + c4);
            *(__half2*)&As[r][c4]     = __floats2half2_rn(v.x, v.y);
            *(__half2*)&As[r][c4 + 2] = __floats2half2_rn(v.z, v.w);
        }
        #pragma unroll
        for (int i = 0; i < 4; i++) {
            int q = tid + i * 256;
            int r = q >> 3;
            int c4 = (q & 7) * 4;
            float4 v = *(const float4*)(W + (size_t)r * NF + k0 + c4);
            *(__half2*)&Ws[r][c4]     = __floats2half2_rn(v.x, v.y);
            *(__half2*)&Ws[r][c4 + 2] = __floats2half2_rn(v.z, v.w);
        }
        __syncthreads();

        #pragma unroll
        for (int ks = 0; ks < 2; ks++) {
            const int kk = ks * 16;
            uint32_t a[2][4], bq[4][2];
            #pragma unroll
            for (int mi = 0; mi < 2; mi++) {
                int ar = wm * 32 + mi * 16 + lr;
                a[mi][0] = *(const uint32_t*)(&As[ar][kk + 2 * lc]);
                a[mi][1] = *(const uint32_t*)(&As[ar + 8][kk + 2 * lc]);
                a[mi][2] = *(const uint32_t*)(&As[ar][kk + 2 * lc + 8]);
                a[mi][3] = *(const uint32_t*)(&As[ar + 8][kk + 2 * lc + 8]);
            }
            #pragma unroll
            for (int ni = 0; ni < 4; ni++) {
                int bc = wn * 32 + ni * 8 + lr;
                bq[ni][0] = *(const uint32_t*)(&Ws[bc][kk + 2 * lc]);
                bq[ni][1] = *(const uint32_t*)(&Ws[bc][kk + 2 * lc + 8]);
            }
            #pragma unroll
            for (int mi = 0; mi < 2; mi++)
                #pragma unroll
                for (int ni = 0; ni < 4; ni++)
                    mma_f16(cacc[mi][ni], a[mi], bq[ni]);
        }
        __syncthreads();
    }

    #pragma unroll
    for (int mi = 0; mi < 2; mi++) {
        #pragma unroll
        for (int ri = 0; ri < 2; ri++) {
            const int gm   = m0 + wm * 32 + mi * 16 + lr + ri * 8;
            const int b    = gm >> 11;
            const int mloc = gm & (NN - 1);
            const float dm = g_d[gm];
            #pragma unroll
            for (int ni = 0; ni < 4; ni++) {
                int f = wn * 32 + ni * 8 + 2 * lc;
                g_yt[(size_t)(b * NF + f)     * NN + mloc] =
                    __float2half_rn(dm * cacc[mi][ni][ri * 2 + 0]);
                g_yt[(size_t)(b * NF + f + 1) * NN + mloc] =
                    __float2half_rn(dm * cacc[mi][ni][ri * 2 + 1]);
            }
        }
    }
}

// ----------------------------------------------------------------
// Kernel 3: out[b,n,f] = d[n] * sum_m adj16[b,n,m] * yt[b,f,m] + bias[f]
// CTA 64(n) x 128(f), K=2048 in 32 chunks of 64.
// 256 threads, 8 warps (2x4), warp tile 32x32, 2 CTAs/SM.
// 3-stage cp.async pipeline; ldmatrix.x4 fragments SOFTWARE-PIPELINED:
//   frags for ks+1 load during HMMAs of ks (double-buffered regs).
// ----------------------------------------------------------------
#define KCH2 64
#define NCH2 (NN / KCH2)       // 32
#define ASTR 72                // halfs per row (144B; conflict-free for LDSM)
#define A_HALFS (64 * ASTR)
#define B_HALFS (128 * ASTR)
#define STAGE_HALFS (A_HALFS + B_HALFS)
#define STAGE_BYTES (STAGE_HALFS * 2)      // 27648
#define SMEM_BYTES (3 * STAGE_BYTES)       // 82944

__global__ __launch_bounds__(256, 2)
void adj_mma_kernel(const float* __restrict__ bias,
                    float* __restrict__ out) {
    extern __shared__ __half hsm[];
    const uint32_t hbase = smem_u32(hsm);

    const int tid  = threadIdx.x;
    const int lane = tid & 31;
    const int wid  = tid >> 5;
    const int wm   = wid >> 2;        // 0..1 over n (32 rows each)
    const int wn   = wid & 3;         // 0..3 over f (32 cols each)
    const int lr   = lane >> 2;
    const int lc   = lane & 3;
    const int row0  = blockIdx.x * 64;
    const int batch = blockIdx.y;

    const __half* Ag = g_adj16 + ((size_t)batch * NN + row0) * NN;
    const __half* Bg = g_yt + (size_t)batch * NF * NN;

    const uint32_t aoff =
        (uint32_t)((wm * 32 + (lane & 7) + ((lane >> 3) & 1) * 8) * ASTR * 2
                   + ((lane >> 4) & 1) * 16);
    const uint32_t boff =
        (uint32_t)((wn * 32 + (lane & 7) + ((lane >> 4) & 1) * 8) * ASTR * 2
                   + ((lane >> 3) & 1) * 16);

    auto issue = [&](int c, int s) {
        __half* As = hsm + s * STAGE_HALFS;
        __half* Bs = As + A_HALFS;
        const int k0 = c * KCH2;
        #pragma unroll
        for (int i = 0; i < 2; i++) {           // A: 64 rows x 64 halfs
            int q = tid + i * 256;
            int r = q >> 3;
            int o = (q & 7) * 8;
            cp16(smem_u32(As + r * ASTR + o), Ag + (size_t)r * NN + k0 + o);
        }
        #pragma unroll
        for (int i = 0; i < 4; i++) {           // B: 128 rows x 64 halfs
            int q = tid + i * 256;
            int r = q >> 3;
            int o = (q & 7) * 8;
            cp16(smem_u32(Bs + r * ASTR + o), Bg + (size_t)r * NN + k0 + o);
        }
        asm volatile("cp.async.commit_group;" ::: "memory");
    };

    float cacc[2][4][4];
    #pragma unroll
    for (int mi = 0; mi < 2; mi++)
        #pragma unroll
        for (int ni = 0; ni < 4; ni++)
            #pragma unroll
            for (int j = 0; j < 4; j++) cacc[mi][ni][j] = 0.f;

    issue(0, 0);
    issue(1, 1);

    for (int c = 0; c < NCH2; c++) {
        const int s = c % 3;
        if (c < NCH2 - 1)
            asm volatile("cp.async.wait_group 1;" ::: "memory");
        else
            asm volatile("cp.async.wait_group 0;" ::: "memory");
        __syncthreads();

        const uint32_t As_u = hbase + s * STAGE_BYTES;
        const uint32_t Bs_u = As_u + A_HALFS * 2;

        // double-buffered fragments: load ks=0, then pipeline ks+1 under ks
        uint32_t a[2][2][4], bt[2][2][4];
        ldsm_x4(a[0][0],  As_u + aoff);
        ldsm_x4(a[0][1],  As_u + aoff + 16 * ASTR * 2);
        ldsm_x4(bt[0][0], Bs_u + boff);
        ldsm_x4(bt[0][1], Bs_u + boff + 16 * ASTR * 2);

        // cp.async for c+2 issued AFTER the first frag loads (off critical path;
        // stage (c+2)%3 was last read in iteration c-1, so it's free).
        if (c + 2 < NCH2) issue(c + 2, (c + 2) % 3);

        #pragma unroll
        for (int ks = 0; ks < 4; ks++) {
            const int cur = ks & 1, nxt = cur ^ 1;
            if (ks < 3) {
                const uint32_t kb = (ks + 1) * 32;    // bytes (16 halfs)
                ldsm_x4(a[nxt][0],  As_u + aoff + kb);
                ldsm_x4(a[nxt][1],  As_u + aoff + 16 * ASTR * 2 + kb);
                ldsm_x4(bt[nxt][0], Bs_u + boff + kb);
                ldsm_x4(bt[nxt][1], Bs_u + boff + 16 * ASTR * 2 + kb);
            }
            #pragma unroll
            for (int mi = 0; mi < 2; mi++)
                #pragma unroll
                for (int ni = 0; ni < 4; ni++)
                    mma_f16(cacc[mi][ni], a[cur][mi],
                            &bt[cur][ni >> 1][(ni & 1) * 2]);
        }
    }

    // ---- epilogue: out = d[n]*acc + bias ----
    #pragma unroll
    for (int mi = 0; mi < 2; mi++) {
        #pragma unroll
        for (int ri = 0; ri < 2; ri++) {
            const int grow = row0 + wm * 32 + mi * 16 + lr + ri * 8;
            const float dn = g_d[batch * NN + grow];
            float* po = out + ((size_t)(batch * NN + grow)) * NF;
            #pragma unroll
            for (int ni = 0; ni < 4; ni++) {
                int f = wn * 32 + ni * 8 + 2 * lc;
                float2 bv = *(const float2*)(bias + f);
                float2 v;
                v.x = dn * cacc[mi][ni][ri * 2 + 0] + bv.x;
                v.y = dn * cacc[mi][ni][ri * 2 + 1] + bv.y;
                *(float2*)(po + f) = v;
            }
        }
    }
}

// ----------------------------------------------------------------
extern "C" void kernel_launch(void* const* d_in, const int* in_sizes, int n_in,
                              void* d_out, int out_size) {
    const float *x = nullptr, *adj = nullptr, *W = nullptr, *bias = nullptr;
    for (int i = 0; i < n_in; i++) {
        int s = in_sizes[i];
        if (s == NB * NN * NN)      adj  = (const float*)d_in[i];
        else if (s == NB * NN * NF) x    = (const float*)d_in[i];
        else if (s == NF * NF)      W    = (const float*)d_in[i];
        else if (s == NF)           bias = (const float*)d_in[i];
    }
    float* out = (float*)d_out;

    cudaFuncSetAttribute(adj_mma_kernel,
                         cudaFuncAttributeMaxDynamicSharedMemorySize, SMEM_BYTES);

    degree_kernel<<<NB * NN / 8, 256>>>(adj);
    xw_kernel<<<NB * NN / 64, 256>>>(x, W);
    adj_mma_kernel<<<dim3(NN / 64, NB), 256, SMEM_BYTES>>>(bias, out);
}